// round 16
// baseline (speedup 1.0000x reference)
#include <cuda_runtime.h>
#include <cuda_bf16.h>
#include <cuda_fp16.h>
#include <cstdint>

#define LSEQ   2048
#define BATCH  16
#define NIN    256
#define LANES  8192
#define LANE4  2048               // 4-lane groups
#define ELEMS  (LSEQ * LANES)
#define NCHUNK 64
#define TCHUNK 32

#define NUSED  2560
#define KEFF   256               // single fp16 GEMM
#define NKCH   4
#define NSTAGE 3
#define STAGE_BYTES 32768
#define EPI_STRIDE 132
#define GEMM_SMEM  (NSTAGE * STAGE_BYTES)

// -------- scratch --------
__device__ __half g_u[5][ELEMS];                // fp16 planes (160MB)
__device__ __half g_xh[32768 * 256];            // A fp16
__device__ __half g_wt[NUSED * KEFF];           // B' fp16 [n-permuted][256]
__device__ float g_A1[NCHUNK * LANES];
__device__ float g_B1[NCHUNK * LANES];
__device__ float g_A2[NCHUNK * LANES];
__device__ float g_B2[NCHUNK * LANES];
__device__ float g_c1in[NCHUNK * LANES];
__device__ float g_c2in[NCHUNK * LANES];

__device__ __forceinline__ float sigmoidf_(float v) {
    return 1.0f / (1.0f + __expf(-v));
}

// ---------------- helpers ----------------
__device__ __forceinline__ uint32_t smem_u32(const void* p) {
    uint32_t a;
    asm("{ .reg .u64 t; cvta.to.shared.u64 t, %1; cvt.u32.u64 %0, t; }" : "=r"(a) : "l"(p));
    return a;
}
__device__ __forceinline__ uint32_t swz(uint32_t b) { return b ^ ((b >> 3) & 0x70); }

__device__ __forceinline__ void cp16(uint32_t dst, const void* src) {
    asm volatile("cp.async.cg.shared.global [%0], [%1], 16;" :: "r"(dst), "l"(src) : "memory");
}
__device__ __forceinline__ void ldsm4(uint32_t* r, uint32_t addr) {
    asm volatile("ldmatrix.sync.aligned.m8n8.x4.shared.b16 {%0,%1,%2,%3}, [%4];"
                 : "=r"(r[0]), "=r"(r[1]), "=r"(r[2]), "=r"(r[3]) : "r"(addr));
}
__device__ __forceinline__ void mma16816h(float* c, const uint32_t* a, const uint32_t* b) {
    asm volatile("mma.sync.aligned.m16n8k16.row.col.f32.f16.f16.f32 "
                 "{%0,%1,%2,%3}, {%4,%5,%6,%7}, {%8,%9}, {%0,%1,%2,%3};"
                 : "+f"(c[0]), "+f"(c[1]), "+f"(c[2]), "+f"(c[3])
                 : "r"(a[0]), "r"(a[1]), "r"(a[2]), "r"(a[3]), "r"(b[0]), "r"(b[1]));
}

// ---------------- merged prep kernel ----------------
__global__ __launch_bounds__(256)
void prep_all(const float4* __restrict__ x, const float* __restrict__ W)
{
    const int b = blockIdx.x;
    if (b < 8192) {
        const int idx = b * 256 + threadIdx.x;
        float4 v = x[idx];
        __half2* hp = (__half2*)g_xh;
        hp[idx * 2 + 0] = __floats2half2_rn(v.x, v.y);
        hp[idx * 2 + 1] = __floats2half2_rn(v.z, v.w);
    } else {
        const int idx = (b - 8192) * 256 + threadIdx.x;
        const int p  = idx >> 8;
        const int ko = idx & 255;
        const int dn = p & 511;
        const int kg = p >> 9;
        const int jg = dn * 6 + kg;
        g_wt[idx] = __float2half_rn(W[(size_t)ko * 3072 + jg]);
    }
}

// ---------------- fp16 HMMA GEMM (R8 exact) ----------------
__global__ __launch_bounds__(256)
void gemm_mma(const float* __restrict__ bias)
{
    extern __shared__ char smem[];
    const uint32_t sb = smem_u32(smem);
    const int tid  = threadIdx.x;
    const int warp = tid >> 5;
    const int lane = tid & 31;
    const int m0 = blockIdx.y * 128;
    const int p0 = blockIdx.x * 128;

    const int wm = warp & 3;
    const int wn = warp >> 2;
    const int rb = wm * 32;
    const int cb = wn * 64;

    const int aRow  = rb + (lane & 7) + ((lane >> 3) & 1) * 8;
    const int aCOff = ((lane >> 4) & 1) * 16;
    const int bRow  = cb + (lane & 7) + ((lane >> 4) & 1) * 8;
    const int bCOff = ((lane >> 3) & 1) * 16;

    float acc[2][8][4];
    #pragma unroll
    for (int i = 0; i < 2; i++)
        #pragma unroll
        for (int j = 0; j < 8; j++)
            #pragma unroll
            for (int k = 0; k < 4; k++) acc[i][j][k] = 0.0f;

    const int lr   = tid >> 3;
    const int lc16 = tid & 7;

    #define LOAD_STAGE(i, s)                                                            \
    do {                                                                                \
        const int kc_ = (i) << 6;                                                       \
        const uint32_t base_ = sb + (uint32_t)(s) * STAGE_BYTES;                        \
        _Pragma("unroll")                                                               \
        for (int j = 0; j < 4; j++) {                                                   \
            const int row_ = lr + j * 32;                                               \
            cp16(base_ + swz((uint32_t)(row_ * 128 + lc16 * 16)),                       \
                 g_xh + (((size_t)(m0 + row_)) << 8) + kc_ + lc16 * 8);                 \
        }                                                                               \
        _Pragma("unroll")                                                               \
        for (int j = 0; j < 4; j++) {                                                   \
            const int row_ = lr + j * 32;                                               \
            cp16(base_ + 16384u + swz((uint32_t)(row_ * 128 + lc16 * 16)),              \
                 g_wt + (size_t)(p0 + row_) * KEFF + kc_ + lc16 * 8);                   \
        }                                                                               \
        asm volatile("cp.async.commit_group;" ::: "memory");                            \
    } while (0)

    LOAD_STAGE(0, 0);
    LOAD_STAGE(1, 1);

    int stage = 0;
    for (int i = 0; i < NKCH; i++) {
        asm volatile("cp.async.wait_group 1;" ::: "memory");
        __syncthreads();

        if (i + 2 < NKCH) {
            const int s2 = (stage + 2 >= NSTAGE) ? (stage + 2 - NSTAGE) : (stage + 2);
            LOAD_STAGE(i + 2, s2);
        }

        const uint32_t aBase = sb + (uint32_t)stage * STAGE_BYTES;
        const uint32_t bBase = aBase + 16384u;

        uint32_t afr[2][2][4];
        uint32_t bfr[2][4][4];
        #pragma unroll
        for (int mf = 0; mf < 2; mf++)
            ldsm4(afr[0][mf], aBase + swz((uint32_t)((aRow + mf * 16) * 128 + aCOff)));
        #pragma unroll
        for (int nf = 0; nf < 4; nf++)
            ldsm4(bfr[0][nf], bBase + swz((uint32_t)((bRow + nf * 16) * 128 + bCOff)));

        #pragma unroll
        for (int ks = 0; ks < 4; ks++) {
            const int cur = ks & 1, nxt = cur ^ 1;
            if (ks < 3) {
                const uint32_t co = (uint32_t)((ks + 1) * 32);
                #pragma unroll
                for (int mf = 0; mf < 2; mf++)
                    ldsm4(afr[nxt][mf], aBase + swz((uint32_t)((aRow + mf * 16) * 128) + co + aCOff));
                #pragma unroll
                for (int nf = 0; nf < 4; nf++)
                    ldsm4(bfr[nxt][nf], bBase + swz((uint32_t)((bRow + nf * 16) * 128) + co + bCOff));
            }
            #pragma unroll
            for (int mf = 0; mf < 2; mf++)
                #pragma unroll
                for (int n8 = 0; n8 < 8; n8++)
                    mma16816h(acc[mf][n8], afr[cur][mf], &bfr[cur][n8 >> 1][(n8 & 1) * 2]);
        }

        stage = (stage + 1 >= NSTAGE) ? 0 : stage + 1;
    }
    #undef LOAD_STAGE

    __syncthreads();

    // -------- epilogue: acc -> smem (fp32) -> fp16 g_u plane --------
    float* smf = (float*)smem;
    {
        const int r0 = rb + (lane >> 2);
        const int c0 = cb + (lane & 3) * 2;
        #pragma unroll
        for (int mf = 0; mf < 2; mf++) {
            const int r = r0 + mf * 16;
            #pragma unroll
            for (int n8 = 0; n8 < 8; n8++) {
                const int c = c0 + n8 * 8;
                *(float2*)&smf[r * EPI_STRIDE + c]       = make_float2(acc[mf][n8][0], acc[mf][n8][1]);
                *(float2*)&smf[(r + 8) * EPI_STRIDE + c] = make_float2(acc[mf][n8][2], acc[mf][n8][3]);
            }
        }
    }
    __syncthreads();

    const int kg  = p0 >> 9;
    const int dnb = p0 & 511;
    __half* plane = g_u[kg];
    const int cc = lane * 4;
    if (kg >= 3) {
        const float* bp = bias + kg * 512 + dnb;
        float4 bv = *(const float4*)(bp + cc);
        #pragma unroll
        for (int t = 0; t < 16; t++) {
            const int r = warp * 16 + t;
            float4 v = *(float4*)&smf[r * EPI_STRIDE + cc];
            __half2 p0h = __floats2half2_rn(sigmoidf_(v.x + bv.x), sigmoidf_(v.y + bv.y));
            __half2 p1h = __floats2half2_rn(sigmoidf_(v.z + bv.z), sigmoidf_(v.w + bv.w));
            uint2 u2;
            u2.x = *(unsigned*)&p0h;
            u2.y = *(unsigned*)&p1h;
            *(uint2*)(plane + (size_t)(m0 + r) * 512 + dnb + cc) = u2;
        }
    } else {
        #pragma unroll
        for (int t = 0; t < 16; t++) {
            const int r = warp * 16 + t;
            float4 v = *(float4*)&smf[r * EPI_STRIDE + cc];
            __half2 p0h = __floats2half2_rn(v.x, v.y);
            __half2 p1h = __floats2half2_rn(v.z, v.w);
            uint2 u2;
            u2.x = *(unsigned*)&p0h;
            u2.y = *(unsigned*)&p1h;
            *(uint2*)(plane + (size_t)(m0 + r) * 512 + dnb + cc) = u2;
        }
    }
}

// ---------------- scan: 4 fp16 lanes per thread (8B loads) ----------------
struct F4 { float v[4]; };
__device__ __forceinline__ F4 h4f(const __half* p, size_t idx4) {
    uint2 raw = *(const uint2*)(p + idx4 * 4);
    __half2 h0 = *(__half2*)&raw.x;
    __half2 h1 = *(__half2*)&raw.y;
    float2 a = __half22float2(h0);
    float2 b = __half22float2(h1);
    F4 r;
    r.v[0] = a.x; r.v[1] = a.y; r.v[2] = b.x; r.v[3] = b.y;
    return r;
}

__global__ __launch_bounds__(256)
void scan_pass1(const float4* __restrict__ d_init4)
{
    const int gid   = blockIdx.x * blockDim.x + threadIdx.x;
    const int l4    = gid & (LANE4 - 1);
    const int chunk = gid >> 11;
    const int dir   = (l4 >> 6) & 1;          // 64 groups of 4 = 256 lanes per dn-half
    const int s0    = chunk * TCHUNK;

    F4 d;
    if (s0 == 0) {
        float4 t = d_init4[l4];
        d.v[0] = t.x; d.v[1] = t.y; d.v[2] = t.z; d.v[3] = t.w;
    } else {
        const int sp = s0 - 1;
        const int tp = dir ? (LSEQ - 1 - sp) : sp;
        d = h4f(g_u[1], (size_t)tp * LANE4 + l4);
    }

    F4 A1, B1, A2, B2;
    #pragma unroll
    for (int k = 0; k < 4; k++) { A1.v[k] = 1.f; B1.v[k] = 0.f; A2.v[k] = 1.f; B2.v[k] = 0.f; }

    #pragma unroll 4
    for (int i = 0; i < TCHUNK; i++) {
        const int s = s0 + i;
        const int t = dir ? (LSEQ - 1 - s) : s;
        const size_t b = (size_t)t * LANE4 + l4;
        F4 x1 = h4f(g_u[0], b);
        F4 x2 = h4f(g_u[1], b);
        F4 x3 = h4f(g_u[2], b);
        F4 f1 = h4f(g_u[3], b);
        F4 f2 = h4f(g_u[4], b);
        #pragma unroll
        for (int k = 0; k < 4; k++) {
            A1.v[k] *= f1.v[k];
            B1.v[k] = f1.v[k] * B1.v[k] + (1.f - f1.v[k]) * x1.v[k];
            const float tmp = x3.v[k] * d.v[k];
            A2.v[k] *= f2.v[k];
            B2.v[k] = f2.v[k] * B2.v[k] + (1.f - f2.v[k]) * tmp;
            d.v[k] = x2.v[k];
        }
    }
    const int o = chunk * LANE4 + l4;
    ((F4*)g_A1)[o] = A1; ((F4*)g_B1)[o] = B1;
    ((F4*)g_A2)[o] = A2; ((F4*)g_B2)[o] = B2;
}

// scalar lanes (8192 threads = 32 CTAs), manual depth-1 prefetch (R15)
__global__ __launch_bounds__(256)
void scan_pass2(const float* __restrict__ c1_init,
                const float* __restrict__ c2_init,
                float* __restrict__ out)
{
    const int l = blockIdx.x * blockDim.x + threadIdx.x;
    float c1 = c1_init[l];
    float c2 = c2_init[l];

    float A1 = g_A1[l], B1 = g_B1[l], A2 = g_A2[l], B2 = g_B2[l];
    for (int c = 0; c < NCHUNK; c++) {
        const int o = c * LANES + l;
        g_c1in[o] = c1;
        g_c2in[o] = c2;
        float nA1, nB1, nA2, nB2;
        if (c + 1 < NCHUNK) {
            const int n = o + LANES;
            nA1 = g_A1[n]; nB1 = g_B1[n];
            nA2 = g_A2[n]; nB2 = g_B2[n];
        }
        c1 = fmaf(A1, c1, B1);
        c2 = fmaf(A2, c2, B2);
        A1 = nA1; B1 = nB1; A2 = nA2; B2 = nB2;
    }

    const size_t tail = (size_t)2 * LSEQ * LANES;
    out[tail + l]         = c1;
    out[tail + LANES + l] = c2;
    const int dir = (l >> 8) & 1;
    const int tlast = dir ? 0 : (LSEQ - 1);
    out[tail + 2 * LANES + l] = __half2float(g_u[1][(size_t)tlast * LANES + l]);
}

__global__ __launch_bounds__(256)
void scan_pass3(const float4* __restrict__ d_init4,
                float* __restrict__ out)
{
    const int gid   = blockIdx.x * blockDim.x + threadIdx.x;
    const int l4    = gid & (LANE4 - 1);
    const int chunk = gid >> 11;
    const int dir   = (l4 >> 6) & 1;
    const int s0    = chunk * TCHUNK;

    F4 d;
    if (s0 == 0) {
        float4 t = d_init4[l4];
        d.v[0] = t.x; d.v[1] = t.y; d.v[2] = t.z; d.v[3] = t.w;
    } else {
        const int sp = s0 - 1;
        const int tp = dir ? (LSEQ - 1 - sp) : sp;
        d = h4f(g_u[1], (size_t)tp * LANE4 + l4);
    }

    const int o = chunk * LANE4 + l4;
    F4 c1 = ((const F4*)g_c1in)[o];
    F4 c2 = ((const F4*)g_c2in)[o];
    float4* out_c1 = (float4*)out;
    float4* out_c2 = out_c1 + (size_t)LSEQ * LANE4;

    #pragma unroll 4
    for (int i = 0; i < TCHUNK; i++) {
        const int s = s0 + i;
        const int t = dir ? (LSEQ - 1 - s) : s;
        const size_t b = (size_t)t * LANE4 + l4;
        F4 x1 = h4f(g_u[0], b);
        F4 x2 = h4f(g_u[1], b);
        F4 x3 = h4f(g_u[2], b);
        F4 f1 = h4f(g_u[3], b);
        F4 f2 = h4f(g_u[4], b);
        float4 o1, o2;
        float* o1p = &o1.x;
        float* o2p = &o2.x;
        #pragma unroll
        for (int k = 0; k < 4; k++) {
            c1.v[k] = (c1.v[k] - x1.v[k]) * f1.v[k] + x1.v[k];
            const float tmp = x3.v[k] * d.v[k];
            c2.v[k] = (c2.v[k] - tmp) * f2.v[k] + tmp;
            d.v[k] = x2.v[k];
            o1p[k] = c1.v[k];
            o2p[k] = c2.v[k];
        }
        out_c1[b] = o1;
        out_c2[b] = o2;
    }
}

// ======================================================================
extern "C" void kernel_launch(void* const* d_in, const int* in_sizes, int n_in,
                              void* d_out, int out_size)
{
    const float* x    = (const float*)d_in[0];
    const float* w    = (const float*)d_in[1];
    const float* bias = (const float*)d_in[2];
    const float* c1i  = (const float*)d_in[3];
    const float* c2i  = (const float*)d_in[4];
    const float* di   = (const float*)d_in[5];
    float* out = (float*)d_out;

    static int attr_set = 0;
    if (!attr_set) {
        cudaFuncSetAttribute(gemm_mma, cudaFuncAttributeMaxDynamicSharedMemorySize, GEMM_SMEM);
        attr_set = 1;
    }

    prep_all<<<8192 + 2560, 256>>>((const float4*)x, w);
    gemm_mma<<<dim3(20, 256), 256, GEMM_SMEM>>>(bias);

    scan_pass1<<<(NCHUNK * LANE4) / 256, 256>>>((const float4*)di);
    scan_pass2<<<LANES / 256, 256>>>(c1i, c2i, out);
    scan_pass3<<<(NCHUNK * LANE4) / 256, 256>>>((const float4*)di, out);
}

// round 17
// speedup vs baseline: 1.0927x; 1.0927x over previous
#include <cuda_runtime.h>
#include <cuda_bf16.h>
#include <cuda_fp16.h>
#include <cstdint>

#define LSEQ   2048
#define BATCH  16
#define NIN    256
#define LANES  8192
#define LANE2  4096
#define ELEMS  (LSEQ * LANES)
#define NCHUNK 64
#define TCHUNK 32

#define NUSED  2560
#define KEFF   256               // single fp16 GEMM
#define NKCH   4
#define NSTAGE 3
#define STAGE_BYTES 32768
#define EPI_STRIDE 132
#define GEMM_SMEM  (NSTAGE * STAGE_BYTES)

// -------- scratch --------
__device__ __half g_u[5][ELEMS];                // fp16 planes (160MB)
__device__ __half g_xh[32768 * 256];            // A fp16
__device__ __half g_wt[NUSED * KEFF];           // B' fp16 [n-permuted][256]
__device__ float g_A1[NCHUNK * LANES];
__device__ float g_B1[NCHUNK * LANES];
__device__ float g_A2[NCHUNK * LANES];
__device__ float g_B2[NCHUNK * LANES];
__device__ float g_c1in[NCHUNK * LANES];
__device__ float g_c2in[NCHUNK * LANES];

__device__ __forceinline__ float sigmoidf_(float v) {
    return 1.0f / (1.0f + __expf(-v));
}

// ---------------- helpers ----------------
__device__ __forceinline__ uint32_t smem_u32(const void* p) {
    uint32_t a;
    asm("{ .reg .u64 t; cvta.to.shared.u64 t, %1; cvt.u32.u64 %0, t; }" : "=r"(a) : "l"(p));
    return a;
}
__device__ __forceinline__ uint32_t swz(uint32_t b) { return b ^ ((b >> 3) & 0x70); }

__device__ __forceinline__ void cp16(uint32_t dst, const void* src) {
    asm volatile("cp.async.cg.shared.global [%0], [%1], 16;" :: "r"(dst), "l"(src) : "memory");
}
__device__ __forceinline__ void ldsm4(uint32_t* r, uint32_t addr) {
    asm volatile("ldmatrix.sync.aligned.m8n8.x4.shared.b16 {%0,%1,%2,%3}, [%4];"
                 : "=r"(r[0]), "=r"(r[1]), "=r"(r[2]), "=r"(r[3]) : "r"(addr));
}
__device__ __forceinline__ void mma16816h(float* c, const uint32_t* a, const uint32_t* b) {
    asm volatile("mma.sync.aligned.m16n8k16.row.col.f32.f16.f16.f32 "
                 "{%0,%1,%2,%3}, {%4,%5,%6,%7}, {%8,%9}, {%0,%1,%2,%3};"
                 : "+f"(c[0]), "+f"(c[1]), "+f"(c[2]), "+f"(c[3])
                 : "r"(a[0]), "r"(a[1]), "r"(a[2]), "r"(a[3]), "r"(b[0]), "r"(b[1]));
}

// ---------------- prep kernels (R8/R15) ----------------
__global__ __launch_bounds__(256)
void cvt_x(const float4* __restrict__ x)
{
    const int idx = blockIdx.x * 256 + threadIdx.x;
    float4 v = x[idx];
    __half2* hp = (__half2*)g_xh;
    hp[idx * 2 + 0] = __floats2half2_rn(v.x, v.y);
    hp[idx * 2 + 1] = __floats2half2_rn(v.z, v.w);
}

__global__ __launch_bounds__(256)
void prep_w(const float* __restrict__ W)   // [256, 3072]
{
    const int idx = blockIdx.x * 256 + threadIdx.x;
    const int p  = idx >> 8;
    const int ko = idx & 255;
    const int dn = p & 511;
    const int kg = p >> 9;
    const int jg = dn * 6 + kg;
    g_wt[idx] = __float2half_rn(W[(size_t)ko * 3072 + jg]);
}

// ---------------- fp16 HMMA GEMM (R8 exact) ----------------
__global__ __launch_bounds__(256)
void gemm_mma(const float* __restrict__ bias)
{
    extern __shared__ char smem[];
    const uint32_t sb = smem_u32(smem);
    const int tid  = threadIdx.x;
    const int warp = tid >> 5;
    const int lane = tid & 31;
    const int m0 = blockIdx.y * 128;
    const int p0 = blockIdx.x * 128;

    const int wm = warp & 3;
    const int wn = warp >> 2;
    const int rb = wm * 32;
    const int cb = wn * 64;

    const int aRow  = rb + (lane & 7) + ((lane >> 3) & 1) * 8;
    const int aCOff = ((lane >> 4) & 1) * 16;
    const int bRow  = cb + (lane & 7) + ((lane >> 4) & 1) * 8;
    const int bCOff = ((lane >> 3) & 1) * 16;

    float acc[2][8][4];
    #pragma unroll
    for (int i = 0; i < 2; i++)
        #pragma unroll
        for (int j = 0; j < 8; j++)
            #pragma unroll
            for (int k = 0; k < 4; k++) acc[i][j][k] = 0.0f;

    const int lr   = tid >> 3;
    const int lc16 = tid & 7;

    #define LOAD_STAGE(i, s)                                                            \
    do {                                                                                \
        const int kc_ = (i) << 6;                                                       \
        const uint32_t base_ = sb + (uint32_t)(s) * STAGE_BYTES;                        \
        _Pragma("unroll")                                                               \
        for (int j = 0; j < 4; j++) {                                                   \
            const int row_ = lr + j * 32;                                               \
            cp16(base_ + swz((uint32_t)(row_ * 128 + lc16 * 16)),                       \
                 g_xh + (((size_t)(m0 + row_)) << 8) + kc_ + lc16 * 8);                 \
        }                                                                               \
        _Pragma("unroll")                                                               \
        for (int j = 0; j < 4; j++) {                                                   \
            const int row_ = lr + j * 32;                                               \
            cp16(base_ + 16384u + swz((uint32_t)(row_ * 128 + lc16 * 16)),              \
                 g_wt + (size_t)(p0 + row_) * KEFF + kc_ + lc16 * 8);                   \
        }                                                                               \
        asm volatile("cp.async.commit_group;" ::: "memory");                            \
    } while (0)

    LOAD_STAGE(0, 0);
    LOAD_STAGE(1, 1);

    int stage = 0;
    for (int i = 0; i < NKCH; i++) {
        asm volatile("cp.async.wait_group 1;" ::: "memory");
        __syncthreads();

        if (i + 2 < NKCH) {
            const int s2 = (stage + 2 >= NSTAGE) ? (stage + 2 - NSTAGE) : (stage + 2);
            LOAD_STAGE(i + 2, s2);
        }

        const uint32_t aBase = sb + (uint32_t)stage * STAGE_BYTES;
        const uint32_t bBase = aBase + 16384u;

        uint32_t afr[2][2][4];
        uint32_t bfr[2][4][4];
        #pragma unroll
        for (int mf = 0; mf < 2; mf++)
            ldsm4(afr[0][mf], aBase + swz((uint32_t)((aRow + mf * 16) * 128 + aCOff)));
        #pragma unroll
        for (int nf = 0; nf < 4; nf++)
            ldsm4(bfr[0][nf], bBase + swz((uint32_t)((bRow + nf * 16) * 128 + bCOff)));

        #pragma unroll
        for (int ks = 0; ks < 4; ks++) {
            const int cur = ks & 1, nxt = cur ^ 1;
            if (ks < 3) {
                const uint32_t co = (uint32_t)((ks + 1) * 32);
                #pragma unroll
                for (int mf = 0; mf < 2; mf++)
                    ldsm4(afr[nxt][mf], aBase + swz((uint32_t)((aRow + mf * 16) * 128) + co + aCOff));
                #pragma unroll
                for (int nf = 0; nf < 4; nf++)
                    ldsm4(bfr[nxt][nf], bBase + swz((uint32_t)((bRow + nf * 16) * 128) + co + bCOff));
            }
            #pragma unroll
            for (int mf = 0; mf < 2; mf++)
                #pragma unroll
                for (int n8 = 0; n8 < 8; n8++)
                    mma16816h(acc[mf][n8], afr[cur][mf], &bfr[cur][n8 >> 1][(n8 & 1) * 2]);
        }

        stage = (stage + 1 >= NSTAGE) ? 0 : stage + 1;
    }
    #undef LOAD_STAGE

    __syncthreads();

    // -------- epilogue: acc -> smem (fp32) -> fp16 g_u plane --------
    float* smf = (float*)smem;
    {
        const int r0 = rb + (lane >> 2);
        const int c0 = cb + (lane & 3) * 2;
        #pragma unroll
        for (int mf = 0; mf < 2; mf++) {
            const int r = r0 + mf * 16;
            #pragma unroll
            for (int n8 = 0; n8 < 8; n8++) {
                const int c = c0 + n8 * 8;
                *(float2*)&smf[r * EPI_STRIDE + c]       = make_float2(acc[mf][n8][0], acc[mf][n8][1]);
                *(float2*)&smf[(r + 8) * EPI_STRIDE + c] = make_float2(acc[mf][n8][2], acc[mf][n8][3]);
            }
        }
    }
    __syncthreads();

    const int kg  = p0 >> 9;
    const int dnb = p0 & 511;
    __half* plane = g_u[kg];
    const int cc = lane * 4;
    if (kg >= 3) {
        const float* bp = bias + kg * 512 + dnb;
        float4 bv = *(const float4*)(bp + cc);
        #pragma unroll
        for (int t = 0; t < 16; t++) {
            const int r = warp * 16 + t;
            float4 v = *(float4*)&smf[r * EPI_STRIDE + cc];
            __half2 p0h = __floats2half2_rn(sigmoidf_(v.x + bv.x), sigmoidf_(v.y + bv.y));
            __half2 p1h = __floats2half2_rn(sigmoidf_(v.z + bv.z), sigmoidf_(v.w + bv.w));
            uint2 u2;
            u2.x = *(unsigned*)&p0h;
            u2.y = *(unsigned*)&p1h;
            *(uint2*)(plane + (size_t)(m0 + r) * 512 + dnb + cc) = u2;
        }
    } else {
        #pragma unroll
        for (int t = 0; t < 16; t++) {
            const int r = warp * 16 + t;
            float4 v = *(float4*)&smf[r * EPI_STRIDE + cc];
            __half2 p0h = __floats2half2_rn(v.x, v.y);
            __half2 p1h = __floats2half2_rn(v.z, v.w);
            uint2 u2;
            u2.x = *(unsigned*)&p0h;
            u2.y = *(unsigned*)&p1h;
            *(uint2*)(plane + (size_t)(m0 + r) * 512 + dnb + cc) = u2;
        }
    }
}

// ---------------- scan (R15 float2 versions) ----------------
__device__ __forceinline__ float2 h2f(const __half* p, size_t idx2) {
    __half2 h = *(const __half2*)(p + idx2 * 2);
    return __half22float2(h);
}

__global__ __launch_bounds__(256)
void scan_pass1(const float2* __restrict__ d_init2)
{
    const int gid   = blockIdx.x * blockDim.x + threadIdx.x;
    const int l2    = gid & (LANE2 - 1);
    const int chunk = gid >> 12;
    const int dir   = (l2 >> 7) & 1;
    const int s0    = chunk * TCHUNK;

    float2 d;
    if (s0 == 0) d = d_init2[l2];
    else {
        const int sp = s0 - 1;
        const int tp = dir ? (LSEQ - 1 - sp) : sp;
        d = h2f(g_u[1], (size_t)tp * LANE2 + l2);
    }

    float2 A1 = {1.f, 1.f}, B1 = {0.f, 0.f}, A2 = {1.f, 1.f}, B2 = {0.f, 0.f};
    #pragma unroll 4
    for (int i = 0; i < TCHUNK; i++) {
        const int s = s0 + i;
        const int t = dir ? (LSEQ - 1 - s) : s;
        const size_t b = (size_t)t * LANE2 + l2;
        float2 x1 = h2f(g_u[0], b);
        float2 x2 = h2f(g_u[1], b);
        float2 x3 = h2f(g_u[2], b);
        float2 f1 = h2f(g_u[3], b);
        float2 f2 = h2f(g_u[4], b);
        A1.x *= f1.x; A1.y *= f1.y;
        B1.x = f1.x * B1.x + (1.f - f1.x) * x1.x;
        B1.y = f1.y * B1.y + (1.f - f1.y) * x1.y;
        float tx = x3.x * d.x, ty = x3.y * d.y;
        A2.x *= f2.x; A2.y *= f2.y;
        B2.x = f2.x * B2.x + (1.f - f2.x) * tx;
        B2.y = f2.y * B2.y + (1.f - f2.y) * ty;
        d = x2;
    }
    const int o = chunk * LANE2 + l2;
    ((float2*)g_A1)[o] = A1; ((float2*)g_B1)[o] = B1;
    ((float2*)g_A2)[o] = A2; ((float2*)g_B2)[o] = B2;
}

// scalar lanes, depth-4 prefetch ring (MLP 16)
__global__ __launch_bounds__(256)
void scan_pass2(const float* __restrict__ c1_init,
                const float* __restrict__ c2_init,
                float* __restrict__ out)
{
    const int l = blockIdx.x * blockDim.x + threadIdx.x;   // 0..8191
    float c1 = c1_init[l];
    float c2 = c2_init[l];

    float pA1[4], pB1[4], pA2[4], pB2[4];
    #pragma unroll
    for (int j = 0; j < 4; j++) {
        const int o = j * LANES + l;
        pA1[j] = g_A1[o]; pB1[j] = g_B1[o];
        pA2[j] = g_A2[o]; pB2[j] = g_B2[o];
    }

    #pragma unroll 4
    for (int c = 0; c < NCHUNK; c++) {
        const int slot = c & 3;
        const int o = c * LANES + l;
        g_c1in[o] = c1;
        g_c2in[o] = c2;
        const float A1 = pA1[slot], B1 = pB1[slot];
        const float A2 = pA2[slot], B2 = pB2[slot];
        if (c + 4 < NCHUNK) {
            const int n = o + 4 * LANES;
            pA1[slot] = g_A1[n]; pB1[slot] = g_B1[n];
            pA2[slot] = g_A2[n]; pB2[slot] = g_B2[n];
        }
        c1 = fmaf(A1, c1, B1);
        c2 = fmaf(A2, c2, B2);
    }

    const size_t tail = (size_t)2 * LSEQ * LANES;
    out[tail + l]         = c1;
    out[tail + LANES + l] = c2;
    const int dir = (l >> 8) & 1;
    const int tlast = dir ? 0 : (LSEQ - 1);
    out[tail + 2 * LANES + l] = __half2float(g_u[1][(size_t)tlast * LANES + l]);
}

__global__ __launch_bounds__(256)
void scan_pass3(const float2* __restrict__ d_init2,
                float* __restrict__ out)
{
    const int gid   = blockIdx.x * blockDim.x + threadIdx.x;
    const int l2    = gid & (LANE2 - 1);
    const int chunk = gid >> 12;
    const int dir   = (l2 >> 7) & 1;
    const int s0    = chunk * TCHUNK;

    float2 d;
    if (s0 == 0) d = d_init2[l2];
    else {
        const int sp = s0 - 1;
        const int tp = dir ? (LSEQ - 1 - sp) : sp;
        d = h2f(g_u[1], (size_t)tp * LANE2 + l2);
    }

    const int o = chunk * LANE2 + l2;
    float2 c1 = ((const float2*)g_c1in)[o];
    float2 c2 = ((const float2*)g_c2in)[o];
    float2* out_c1 = (float2*)out;
    float2* out_c2 = out_c1 + (size_t)LSEQ * LANE2;

    #pragma unroll 4
    for (int i = 0; i < TCHUNK; i++) {
        const int s = s0 + i;
        const int t = dir ? (LSEQ - 1 - s) : s;
        const size_t b = (size_t)t * LANE2 + l2;
        float2 x1 = h2f(g_u[0], b);
        float2 x2 = h2f(g_u[1], b);
        float2 x3 = h2f(g_u[2], b);
        float2 f1 = h2f(g_u[3], b);
        float2 f2 = h2f(g_u[4], b);
        c1.x = (c1.x - x1.x) * f1.x + x1.x;
        c1.y = (c1.y - x1.y) * f1.y + x1.y;
        float tx = x3.x * d.x, ty = x3.y * d.y;
        c2.x = (c2.x - tx) * f2.x + tx;
        c2.y = (c2.y - ty) * f2.y + ty;
        d = x2;
        out_c1[b] = c1;
        out_c2[b] = c2;
    }
}

// ======================================================================
extern "C" void kernel_launch(void* const* d_in, const int* in_sizes, int n_in,
                              void* d_out, int out_size)
{
    const float* x    = (const float*)d_in[0];
    const float* w    = (const float*)d_in[1];
    const float* bias = (const float*)d_in[2];
    const float* c1i  = (const float*)d_in[3];
    const float* c2i  = (const float*)d_in[4];
    const float* di   = (const float*)d_in[5];
    float* out = (float*)d_out;

    static int attr_set = 0;
    if (!attr_set) {
        cudaFuncSetAttribute(gemm_mma, cudaFuncAttributeMaxDynamicSharedMemorySize, GEMM_SMEM);
        attr_set = 1;
    }

    cvt_x<<<8192, 256>>>((const float4*)x);
    prep_w<<<2560, 256>>>(w);
    gemm_mma<<<dim3(20, 256), 256, GEMM_SMEM>>>(bias);

    scan_pass1<<<(NCHUNK * LANE2) / 256, 256>>>((const float2*)di);
    scan_pass2<<<LANES / 256, 256>>>(c1i, c2i, out);
    scan_pass3<<<(NCHUNK * LANE2) / 256, 256>>>((const float2*)di, out);
}